// round 2
// baseline (speedup 1.0000x reference)
#include <cuda_runtime.h>
#include <cuda_bf16.h>
#include <cstdint>

namespace {
constexpr int kC = 256;
constexpr int kTokens = 2048 * 64;               // 131072 window-tokens
constexpr float kScale = 0.17677669529663687f;   // 32^-0.5
constexpr int XS = 264;                          // smem row stride (bf16 elems), 16B aligned, conflict-free
}

__device__ __nv_bfloat16 g_X[(size_t)kTokens * kC];   // LN'd + shuffled + windowed input
__device__ __nv_bfloat16 g_O[(size_t)kTokens * kC];   // attention output (pre out-proj)
__device__ __nv_bfloat16 g_W[4 * kC * kC];            // Wq, Wk, Wv, Wp bf16

__device__ __forceinline__ uint32_t sptr(const void* p) {
  return (uint32_t)__cvta_generic_to_shared(p);
}
__device__ __forceinline__ void ldm4(uint32_t r[4], uint32_t a) {
  asm volatile("ldmatrix.sync.aligned.m8n8.x4.shared.b16 {%0,%1,%2,%3}, [%4];"
               : "=r"(r[0]), "=r"(r[1]), "=r"(r[2]), "=r"(r[3]) : "r"(a));
}
__device__ __forceinline__ void ldm4t(uint32_t r[4], uint32_t a) {
  asm volatile("ldmatrix.sync.aligned.m8n8.x4.trans.shared.b16 {%0,%1,%2,%3}, [%4];"
               : "=r"(r[0]), "=r"(r[1]), "=r"(r[2]), "=r"(r[3]) : "r"(a));
}
__device__ __forceinline__ void mma16816(float c[4], const uint32_t a[4], const uint32_t b[2]) {
  asm volatile("mma.sync.aligned.m16n8k16.row.col.f32.bf16.bf16.f32 "
               "{%0,%1,%2,%3}, {%4,%5,%6,%7}, {%8,%9}, {%0,%1,%2,%3};"
               : "+f"(c[0]), "+f"(c[1]), "+f"(c[2]), "+f"(c[3])
               : "r"(a[0]), "r"(a[1]), "r"(a[2]), "r"(a[3]), "r"(b[0]), "r"(b[1]));
}
__device__ __forceinline__ uint32_t packbf(float x, float y) {
  __nv_bfloat162 t = __floats2bfloat162_rn(x, y);
  return reinterpret_cast<uint32_t&>(t);
}

// ---------------- K0: weights fp32 -> bf16 ----------------
__global__ void k_convert(const float* __restrict__ Wq, const float* __restrict__ Wk,
                          const float* __restrict__ Wv, const float* __restrict__ Wp) {
  int i = blockIdx.x * blockDim.x + threadIdx.x;
  constexpr int n = kC * kC;
  g_W[i]         = __float2bfloat16(Wq[i]);
  g_W[n + i]     = __float2bfloat16(Wk[i]);
  g_W[2 * n + i] = __float2bfloat16(Wv[i]);
  g_W[3 * n + i] = __float2bfloat16(Wp[i]);
}

// ---------------- K1: LN + shuffle + window partition ----------------
__global__ void k_ln(const float* __restrict__ x, const int* __restrict__ pn,
                     const int* __restrict__ pt, const float* __restrict__ gam,
                     const float* __restrict__ bet) {
  int m = blockIdx.x * 8 + (threadIdx.x >> 5);
  int lane = threadIdx.x & 31;
  int w = m >> 6, l = m & 63;
  int b = w >> 9, rem = w & 511;
  int n = (rem >> 6) * 8 + (l >> 3);   // nb_blk*FW + fw
  int t = (rem & 63) * 8 + (l & 7);    // t_blk*TW + tw
  int sn = __ldg(pn + b * 64 + n);
  int st = __ldg(pt + b * 512 + t);
  const float* src = x + ((size_t)((b * 64 + sn) * 512 + st)) * kC + lane * 8;
  float4 p0 = *(const float4*)(src);
  float4 p1 = *(const float4*)(src + 4);
  float s = p0.x + p0.y + p0.z + p0.w + p1.x + p1.y + p1.z + p1.w;
  float ss = p0.x * p0.x + p0.y * p0.y + p0.z * p0.z + p0.w * p0.w
           + p1.x * p1.x + p1.y * p1.y + p1.z * p1.z + p1.w * p1.w;
  #pragma unroll
  for (int o = 16; o; o >>= 1) {
    s  += __shfl_xor_sync(~0u, s,  o);
    ss += __shfl_xor_sync(~0u, ss, o);
  }
  float mean = s * (1.f / 256.f);
  float inv = rsqrtf(ss * (1.f / 256.f) - mean * mean + 1e-5f);
  int c0 = lane * 8;
  float4 g0 = *(const float4*)(gam + c0);
  float4 g1 = *(const float4*)(gam + c0 + 4);
  float4 b0 = *(const float4*)(bet + c0);
  float4 b1 = *(const float4*)(bet + c0 + 4);
  uint4 r;
  r.x = packbf((p0.x - mean) * inv * g0.x + b0.x, (p0.y - mean) * inv * g0.y + b0.y);
  r.y = packbf((p0.z - mean) * inv * g0.z + b0.z, (p0.w - mean) * inv * g0.w + b0.w);
  r.z = packbf((p1.x - mean) * inv * g1.x + b1.x, (p1.y - mean) * inv * g1.y + b1.y);
  r.w = packbf((p1.z - mean) * inv * g1.z + b1.z, (p1.w - mean) * inv * g1.w + b1.w);
  *(uint4*)(g_X + (size_t)m * kC + c0) = r;
}

// ---------------- K2: fused QKV projection + windowed attention ----------------
// block = 2 windows (128 tokens), 8 warps. smem: X,K,V 128x256 + 32x256 weight stage.
__global__ __launch_bounds__(256, 1) void k_fused(const float* __restrict__ bq,
                                                  const float* __restrict__ bk,
                                                  const float* __restrict__ bv) {
  extern __shared__ __nv_bfloat16 sm[];
  __nv_bfloat16* sX = sm;
  __nv_bfloat16* sK = sm + 128 * XS;
  __nv_bfloat16* sV = sm + 256 * XS;
  __nv_bfloat16* sW = sm + 384 * XS;
  const uint32_t uX = sptr(sX), uK = sptr(sK), uV = sptr(sV), uW = sptr(sW);
  const int tid = threadIdx.x, w = tid >> 5, lane = tid & 31;
  const int g = lane >> 2, tig = lane & 3;

  const int aRow = lane & 15, aCol = (lane >> 4) << 3;                        // A 16x16
  const int bN = ((lane >> 4) << 3) + (lane & 7), bK = ((lane >> 3) & 1) << 3; // B: 2 n-tiles x k16
  const int b2N = lane & 7, b2K = (lane >> 3) << 3;                            // B: 1 n-tile x 2 k-steps
  const int tK = (((lane >> 3) & 1) << 3) + (lane & 7), tN = (lane >> 4) << 3; // trans-B

  {
    const uint4* gx = (const uint4*)(g_X + (size_t)blockIdx.x * 128 * kC);
    #pragma unroll
    for (int i = 0; i < 16; i++) {
      int ch = tid + 256 * i;
      *(uint4*)(sX + (ch >> 5) * XS + (ch & 31) * 8) = gx[ch];
    }
  }

  // ---- K and V projections into smem ----
  #pragma unroll 1
  for (int mm = 0; mm < 2; mm++) {
    const __nv_bfloat16* Wg = g_W + (1 + mm) * (kC * kC);
    const float* bias = (mm == 0) ? bk : bv;
    __nv_bfloat16* sOut = (mm == 0) ? sK : sV;
    #pragma unroll 1
    for (int nc = 0; nc < 8; nc++) {
      __syncthreads();
      const uint4* gw = (const uint4*)(Wg + nc * 32 * kC);
      #pragma unroll
      for (int i = 0; i < 4; i++) {
        int ch = tid + 256 * i;
        *(uint4*)(sW + (ch >> 5) * XS + (ch & 31) * 8) = gw[ch];
      }
      __syncthreads();
      float c[4][4] = {};
      const int m0 = 16 * w;
      #pragma unroll
      for (int k0 = 0; k0 < 256; k0 += 16) {
        uint32_t a[4], bb0[4], bb1[4];
        ldm4(a,   uX + (uint32_t)(((m0 + aRow) * XS + k0 + aCol) * 2));
        ldm4(bb0, uW + (uint32_t)((bN * XS + k0 + bK) * 2));
        ldm4(bb1, uW + (uint32_t)(((16 + bN) * XS + k0 + bK) * 2));
        mma16816(c[0], a, bb0); mma16816(c[1], a, bb0 + 2);
        mma16816(c[2], a, bb1); mma16816(c[3], a, bb1 + 2);
      }
      #pragma unroll
      for (int nt = 0; nt < 4; nt++) {
        int col = nc * 32 + nt * 8 + tig * 2;
        float e0 = __ldg(bias + col), e1 = __ldg(bias + col + 1);
        *(uint32_t*)(sOut + (m0 + g) * XS + col)     = packbf(c[nt][0] + e0, c[nt][1] + e1);
        *(uint32_t*)(sOut + (m0 + 8 + g) * XS + col) = packbf(c[nt][2] + e0, c[nt][3] + e1);
      }
    }
  }

  // ---- per-head: Q proj + S=QK^T + softmax + O=PV ----
  const int wi = w >> 2;                 // which window
  const int lr = 64 * wi + 16 * (w & 3); // this warp's 16 query rows
  #pragma unroll 1
  for (int h = 0; h < 8; h++) {
    __syncthreads();
    {
      const uint4* gw = (const uint4*)(g_W + h * 32 * kC);  // Wq head slice
      #pragma unroll
      for (int i = 0; i < 4; i++) {
        int ch = tid + 256 * i;
        *(uint4*)(sW + (ch >> 5) * XS + (ch & 31) * 8) = gw[ch];
      }
    }
    __syncthreads();
    float qc[4][4] = {};
    #pragma unroll
    for (int k0 = 0; k0 < 256; k0 += 16) {
      uint32_t a[4], bb0[4], bb1[4];
      ldm4(a,   uX + (uint32_t)(((lr + aRow) * XS + k0 + aCol) * 2));
      ldm4(bb0, uW + (uint32_t)((bN * XS + k0 + bK) * 2));
      ldm4(bb1, uW + (uint32_t)(((16 + bN) * XS + k0 + bK) * 2));
      mma16816(qc[0], a, bb0); mma16816(qc[1], a, bb0 + 2);
      mma16816(qc[2], a, bb1); mma16816(qc[3], a, bb1 + 2);
    }
    uint32_t aQ[2][4];
    #pragma unroll
    for (int kt = 0; kt < 2; kt++) {
      #pragma unroll
      for (int j = 0; j < 2; j++) {
        int nt = 2 * kt + j;
        int col = h * 32 + nt * 8 + tig * 2;
        float e0 = __ldg(bq + col), e1 = __ldg(bq + col + 1);
        aQ[kt][2 * j]     = packbf((qc[nt][0] + e0) * kScale, (qc[nt][1] + e1) * kScale);
        aQ[kt][2 * j + 1] = packbf((qc[nt][2] + e0) * kScale, (qc[nt][3] + e1) * kScale);
      }
    }
    float s[8][4];
    #pragma unroll
    for (int nt = 0; nt < 8; nt++) {
      s[nt][0] = s[nt][1] = s[nt][2] = s[nt][3] = 0.f;
      uint32_t bb[4];
      ldm4(bb, uK + (uint32_t)(((64 * wi + nt * 8 + b2N) * XS + h * 32 + b2K) * 2));
      mma16816(s[nt], aQ[0], bb);
      mma16816(s[nt], aQ[1], bb + 2);
    }
    float mx0 = -1e30f, mx1 = -1e30f;
    #pragma unroll
    for (int nt = 0; nt < 8; nt++) {
      mx0 = fmaxf(mx0, fmaxf(s[nt][0], s[nt][1]));
      mx1 = fmaxf(mx1, fmaxf(s[nt][2], s[nt][3]));
    }
    mx0 = fmaxf(mx0, __shfl_xor_sync(~0u, mx0, 1)); mx0 = fmaxf(mx0, __shfl_xor_sync(~0u, mx0, 2));
    mx1 = fmaxf(mx1, __shfl_xor_sync(~0u, mx1, 1)); mx1 = fmaxf(mx1, __shfl_xor_sync(~0u, mx1, 2));
    float sm0 = 0.f, sm1 = 0.f;
    #pragma unroll
    for (int nt = 0; nt < 8; nt++) {
      s[nt][0] = __expf(s[nt][0] - mx0); s[nt][1] = __expf(s[nt][1] - mx0);
      s[nt][2] = __expf(s[nt][2] - mx1); s[nt][3] = __expf(s[nt][3] - mx1);
      sm0 += s[nt][0] + s[nt][1]; sm1 += s[nt][2] + s[nt][3];
    }
    sm0 += __shfl_xor_sync(~0u, sm0, 1); sm0 += __shfl_xor_sync(~0u, sm0, 2);
    sm1 += __shfl_xor_sync(~0u, sm1, 1); sm1 += __shfl_xor_sync(~0u, sm1, 2);
    float r0 = __frcp_rn(sm0), r1 = __frcp_rn(sm1);
    uint32_t aP[4][4];
    #pragma unroll
    for (int kt = 0; kt < 4; kt++) {
      aP[kt][0] = packbf(s[2 * kt][0] * r0, s[2 * kt][1] * r0);
      aP[kt][1] = packbf(s[2 * kt][2] * r1, s[2 * kt][3] * r1);
      aP[kt][2] = packbf(s[2 * kt + 1][0] * r0, s[2 * kt + 1][1] * r0);
      aP[kt][3] = packbf(s[2 * kt + 1][2] * r1, s[2 * kt + 1][3] * r1);
    }
    float o[4][4] = {};
    #pragma unroll
    for (int ks = 0; ks < 4; ks++) {
      uint32_t bb0[4], bb1[4];
      ldm4t(bb0, uV + (uint32_t)(((64 * wi + ks * 16 + tK) * XS + h * 32 + tN) * 2));
      ldm4t(bb1, uV + (uint32_t)(((64 * wi + ks * 16 + tK) * XS + h * 32 + 16 + tN) * 2));
      mma16816(o[0], aP[ks], bb0); mma16816(o[1], aP[ks], bb0 + 2);
      mma16816(o[2], aP[ks], bb1); mma16816(o[3], aP[ks], bb1 + 2);
    }
    __nv_bfloat16* dst = g_O + ((size_t)blockIdx.x * 128 + lr) * kC + h * 32;
    #pragma unroll
    for (int nt = 0; nt < 4; nt++) {
      int col = nt * 8 + tig * 2;
      *(uint32_t*)(dst + (size_t)g * kC + col)       = packbf(o[nt][0], o[nt][1]);
      *(uint32_t*)(dst + (size_t)(8 + g) * kC + col) = packbf(o[nt][2], o[nt][3]);
    }
  }
}

// ---------------- K3: out-projection + inverse scatter + residual ----------------
__global__ __launch_bounds__(256, 1) void k_proj(const float* __restrict__ inpt,
                                                 const int* __restrict__ pn,
                                                 const int* __restrict__ pt,
                                                 const float* __restrict__ bp,
                                                 float* __restrict__ out) {
  extern __shared__ __nv_bfloat16 sm[];
  __nv_bfloat16* sA = sm;
  __nv_bfloat16* sB = sm + 128 * XS;
  int* sDest = (int*)(sm + 256 * XS);
  const uint32_t uA = sptr(sA), uB = sptr(sB);
  const int tid = threadIdx.x, w = tid >> 5, lane = tid & 31;
  const int g = lane >> 2, tig = lane & 3;
  const int aRow = lane & 15, aCol = (lane >> 4) << 3;
  const int bN = ((lane >> 4) << 3) + (lane & 7), bK = ((lane >> 3) & 1) << 3;
  const int m0 = blockIdx.x * 128, n0 = blockIdx.y * 128;
  {
    const uint4* ga = (const uint4*)(g_O + (size_t)m0 * kC);
    const uint4* gb = (const uint4*)(g_W + 3 * kC * kC + (size_t)n0 * kC);
    #pragma unroll
    for (int i = 0; i < 16; i++) {
      int ch = tid + 256 * i;
      *(uint4*)(sA + (ch >> 5) * XS + (ch & 31) * 8) = ga[ch];
      *(uint4*)(sB + (ch >> 5) * XS + (ch & 31) * 8) = gb[ch];
    }
  }
  if (tid < 128) {
    int m = m0 + tid;
    int ww = m >> 6, l = m & 63;
    int b = ww >> 9, rem = ww & 511;
    int n = (rem >> 6) * 8 + (l >> 3);
    int t = (rem & 63) * 8 + (l & 7);
    sDest[tid] = ((b * 64 + __ldg(pn + b * 64 + n)) * 512 + __ldg(pt + b * 512 + t)) * kC;
  }
  __syncthreads();
  const int wm = (w >> 1) * 32, wn = (w & 1) * 64;
  float c[2][8][4] = {};
  #pragma unroll
  for (int k0 = 0; k0 < 256; k0 += 16) {
    uint32_t a0[4], a1[4];
    ldm4(a0, uA + (uint32_t)(((wm + aRow) * XS + k0 + aCol) * 2));
    ldm4(a1, uA + (uint32_t)(((wm + 16 + aRow) * XS + k0 + aCol) * 2));
    #pragma unroll
    for (int j = 0; j < 4; j++) {
      uint32_t bb[4];
      ldm4(bb, uB + (uint32_t)(((wn + j * 16 + bN) * XS + k0 + bK) * 2));
      mma16816(c[0][2 * j], a0, bb); mma16816(c[0][2 * j + 1], a0, bb + 2);
      mma16816(c[1][2 * j], a1, bb); mma16816(c[1][2 * j + 1], a1, bb + 2);
    }
  }
  #pragma unroll
  for (int mt = 0; mt < 2; mt++) {
    #pragma unroll
    for (int nt = 0; nt < 8; nt++) {
      int colg = n0 + wn + nt * 8 + tig * 2;
      float e0 = __ldg(bp + colg), e1 = __ldg(bp + colg + 1);
      int row = wm + mt * 16 + g;
      {
        size_t d = (size_t)sDest[row] + colg;
        float2 iv = *(const float2*)(inpt + d);
        float2 r = {c[mt][nt][0] + e0 + iv.x, c[mt][nt][1] + e1 + iv.y};
        *(float2*)(out + d) = r;
      }
      {
        size_t d = (size_t)sDest[row + 8] + colg;
        float2 iv = *(const float2*)(inpt + d);
        float2 r = {c[mt][nt][2] + e0 + iv.x, c[mt][nt][3] + e1 + iv.y};
        *(float2*)(out + d) = r;
      }
    }
  }
}

extern "C" void kernel_launch(void* const* d_in, const int* in_sizes, int n_in,
                              void* d_out, int out_size) {
  const float* inpt = (const float*)d_in[0];
  const int*   pn   = (const int*)d_in[1];
  const int*   pt   = (const int*)d_in[2];
  const float* ln_g = (const float*)d_in[3];
  const float* ln_b = (const float*)d_in[4];
  const float* Wq   = (const float*)d_in[5];
  const float* bq   = (const float*)d_in[6];
  const float* Wk   = (const float*)d_in[7];
  const float* bk   = (const float*)d_in[8];
  const float* Wv   = (const float*)d_in[9];
  const float* bv   = (const float*)d_in[10];
  const float* Wp   = (const float*)d_in[11];
  const float* bp   = (const float*)d_in[12];
  float* out = (float*)d_out;
  (void)in_sizes; (void)n_in; (void)out_size;

  const int smem_fused = 416 * XS * 2;            // 219648 B
  const int smem_proj  = 256 * XS * 2 + 128 * 4;  // 135680 B
  cudaFuncSetAttribute(k_fused, cudaFuncAttributeMaxDynamicSharedMemorySize, smem_fused);
  cudaFuncSetAttribute(k_proj,  cudaFuncAttributeMaxDynamicSharedMemorySize, smem_proj);

  k_convert<<<256, 256>>>(Wq, Wk, Wv, Wp);
  k_ln<<<kTokens / 8, 256>>>(inpt, pn, pt, ln_g, ln_b);
  k_fused<<<1024, 256, smem_fused>>>(bq, bk, bv);
  k_proj<<<dim3(1024, 2), 256, smem_proj>>>(inpt, pn, pt, bp, out);
}

// round 3
// speedup vs baseline: 1.1194x; 1.1194x over previous
#include <cuda_runtime.h>
#include <cuda_bf16.h>
#include <cstdint>

namespace {
constexpr int kC = 256;
constexpr int kTokens = 2048 * 64;               // 131072 window-tokens
constexpr float kScale = 0.17677669529663687f;   // 32^-0.5
}

__device__ __nv_bfloat16 g_X[(size_t)kTokens * kC];   // LN'd + shuffled + windowed input
__device__ __nv_bfloat16 g_O[(size_t)kTokens * kC];   // attention output (pre out-proj)
__device__ __nv_bfloat16 g_W[4 * kC * kC];            // Wq, Wk, Wv, Wp bf16

__device__ __forceinline__ uint32_t sptr(const void* p) {
  return (uint32_t)__cvta_generic_to_shared(p);
}
// XOR-swizzled address: tile rows are 512B (256 bf16). c = bf16 column (multiple of 8).
__device__ __forceinline__ uint32_t swz(uint32_t base, int r, int c) {
  return base + (uint32_t)(r * 512 + ((((c >> 3) ^ (r & 7))) << 4));
}
__device__ __forceinline__ void ldm4(uint32_t r[4], uint32_t a) {
  asm volatile("ldmatrix.sync.aligned.m8n8.x4.shared.b16 {%0,%1,%2,%3}, [%4];"
               : "=r"(r[0]), "=r"(r[1]), "=r"(r[2]), "=r"(r[3]) : "r"(a));
}
__device__ __forceinline__ void ldm4t(uint32_t r[4], uint32_t a) {
  asm volatile("ldmatrix.sync.aligned.m8n8.x4.trans.shared.b16 {%0,%1,%2,%3}, [%4];"
               : "=r"(r[0]), "=r"(r[1]), "=r"(r[2]), "=r"(r[3]) : "r"(a));
}
__device__ __forceinline__ void mma16816(float c[4], const uint32_t a[4], const uint32_t b[2]) {
  asm volatile("mma.sync.aligned.m16n8k16.row.col.f32.bf16.bf16.f32 "
               "{%0,%1,%2,%3}, {%4,%5,%6,%7}, {%8,%9}, {%0,%1,%2,%3};"
               : "+f"(c[0]), "+f"(c[1]), "+f"(c[2]), "+f"(c[3])
               : "r"(a[0]), "r"(a[1]), "r"(a[2]), "r"(a[3]), "r"(b[0]), "r"(b[1]));
}
__device__ __forceinline__ uint32_t packbf(float x, float y) {
  __nv_bfloat162 t = __floats2bfloat162_rn(x, y);
  return reinterpret_cast<uint32_t&>(t);
}
__device__ __forceinline__ void cpa16(uint32_t d, const void* s) {
  asm volatile("cp.async.cg.shared.global [%0], [%1], 16;" :: "r"(d), "l"(s));
}
__device__ __forceinline__ void cpa_commit() {
  asm volatile("cp.async.commit_group;" ::: "memory");
}

// ---------------- K0: weights fp32 -> bf16 ----------------
__global__ void k_convert(const float* __restrict__ Wq, const float* __restrict__ Wk,
                          const float* __restrict__ Wv, const float* __restrict__ Wp) {
  int i = blockIdx.x * blockDim.x + threadIdx.x;
  constexpr int n = kC * kC;
  g_W[i]         = __float2bfloat16(Wq[i]);
  g_W[n + i]     = __float2bfloat16(Wk[i]);
  g_W[2 * n + i] = __float2bfloat16(Wv[i]);
  g_W[3 * n + i] = __float2bfloat16(Wp[i]);
}

// ---------------- K1: LN + shuffle + window partition ----------------
__global__ void k_ln(const float* __restrict__ x, const int* __restrict__ pn,
                     const int* __restrict__ pt, const float* __restrict__ gam,
                     const float* __restrict__ bet) {
  int m = blockIdx.x * 8 + (threadIdx.x >> 5);
  int lane = threadIdx.x & 31;
  int w = m >> 6, l = m & 63;
  int b = w >> 9, rem = w & 511;
  int n = (rem >> 6) * 8 + (l >> 3);
  int t = (rem & 63) * 8 + (l & 7);
  int sn = __ldg(pn + b * 64 + n);
  int st = __ldg(pt + b * 512 + t);
  const float* src = x + ((size_t)((b * 64 + sn) * 512 + st)) * kC + lane * 8;
  float4 p0 = *(const float4*)(src);
  float4 p1 = *(const float4*)(src + 4);
  float s = p0.x + p0.y + p0.z + p0.w + p1.x + p1.y + p1.z + p1.w;
  float ss = p0.x * p0.x + p0.y * p0.y + p0.z * p0.z + p0.w * p0.w
           + p1.x * p1.x + p1.y * p1.y + p1.z * p1.z + p1.w * p1.w;
  #pragma unroll
  for (int o = 16; o; o >>= 1) {
    s  += __shfl_xor_sync(~0u, s,  o);
    ss += __shfl_xor_sync(~0u, ss, o);
  }
  float mean = s * (1.f / 256.f);
  float inv = rsqrtf(ss * (1.f / 256.f) - mean * mean + 1e-5f);
  int c0 = lane * 8;
  float4 g0 = *(const float4*)(gam + c0);
  float4 g1 = *(const float4*)(gam + c0 + 4);
  float4 b0 = *(const float4*)(bet + c0);
  float4 b1 = *(const float4*)(bet + c0 + 4);
  uint4 r;
  r.x = packbf((p0.x - mean) * inv * g0.x + b0.x, (p0.y - mean) * inv * g0.y + b0.y);
  r.y = packbf((p0.z - mean) * inv * g0.z + b0.z, (p0.w - mean) * inv * g0.w + b0.w);
  r.z = packbf((p1.x - mean) * inv * g1.x + b1.x, (p1.y - mean) * inv * g1.y + b1.y);
  r.w = packbf((p1.z - mean) * inv * g1.z + b1.z, (p1.w - mean) * inv * g1.w + b1.w);
  *(uint4*)(g_X + (size_t)m * kC + c0) = r;
}

// ---------------- K2 helpers ----------------
// project 128 rows x 32 cols (chunk nc) from sX (swizzled) with weight buffer uWb
__device__ __forceinline__ void proj_chunk(uint32_t uX, uint32_t uWb, uint32_t uOut,
                                           const float* __restrict__ bias, int nc,
                                           int w, int lane) {
  const int g = lane >> 2, tig = lane & 3;
  const int aRow = lane & 15, aCol = (lane >> 4) << 3;
  const int bN = ((lane >> 4) << 3) + (lane & 7), bK = ((lane >> 3) & 1) << 3;
  const int m0 = 16 * w;
  float c[4][4] = {};
  #pragma unroll
  for (int k0 = 0; k0 < 256; k0 += 16) {
    uint32_t a[4], bb0[4], bb1[4];
    ldm4(a,   swz(uX,  m0 + aRow, k0 + aCol));
    ldm4(bb0, swz(uWb, bN,        k0 + bK));
    ldm4(bb1, swz(uWb, 16 + bN,   k0 + bK));
    mma16816(c[0], a, bb0); mma16816(c[1], a, bb0 + 2);
    mma16816(c[2], a, bb1); mma16816(c[3], a, bb1 + 2);
  }
  #pragma unroll
  for (int nt = 0; nt < 4; nt++) {
    int col = nc * 32 + nt * 8;
    float e0 = __ldg(bias + col + tig * 2), e1 = __ldg(bias + col + tig * 2 + 1);
    *(uint32_t*)(__cvta_shared_to_generic(swz(uOut, m0 + g,     col) + tig * 4))
        = packbf(c[nt][0] + e0, c[nt][1] + e1);
    *(uint32_t*)(__cvta_shared_to_generic(swz(uOut, m0 + 8 + g, col) + tig * 4))
        = packbf(c[nt][2] + e0, c[nt][3] + e1);
  }
}

// Q-proj + attention for head h; weight buffer holds Wq rows [h*32, h*32+32)
__device__ __forceinline__ void head_attn(uint32_t uX, uint32_t uWb, uint32_t uK, uint32_t uV,
                                          const float* __restrict__ bq, int h,
                                          int w, int lane, __nv_bfloat16* __restrict__ gO) {
  const int g = lane >> 2, tig = lane & 3;
  const int aRow = lane & 15, aCol = (lane >> 4) << 3;
  const int bN = ((lane >> 4) << 3) + (lane & 7), bK = ((lane >> 3) & 1) << 3;
  const int b2N = lane & 7, b2K = (lane >> 3) << 3;
  const int tK = (((lane >> 3) & 1) << 3) + (lane & 7), tN = (lane >> 4) << 3;
  const int wi = w >> 2;
  const int lr = 64 * wi + 16 * (w & 3);

  float qc[4][4] = {};
  #pragma unroll
  for (int k0 = 0; k0 < 256; k0 += 16) {
    uint32_t a[4], bb0[4], bb1[4];
    ldm4(a,   swz(uX,  lr + aRow, k0 + aCol));
    ldm4(bb0, swz(uWb, bN,        k0 + bK));
    ldm4(bb1, swz(uWb, 16 + bN,   k0 + bK));
    mma16816(qc[0], a, bb0); mma16816(qc[1], a, bb0 + 2);
    mma16816(qc[2], a, bb1); mma16816(qc[3], a, bb1 + 2);
  }
  uint32_t aQ[2][4];
  #pragma unroll
  for (int kt = 0; kt < 2; kt++) {
    #pragma unroll
    for (int j = 0; j < 2; j++) {
      int nt = 2 * kt + j;
      int col = h * 32 + nt * 8 + tig * 2;
      float e0 = __ldg(bq + col), e1 = __ldg(bq + col + 1);
      aQ[kt][2 * j]     = packbf((qc[nt][0] + e0) * kScale, (qc[nt][1] + e1) * kScale);
      aQ[kt][2 * j + 1] = packbf((qc[nt][2] + e0) * kScale, (qc[nt][3] + e1) * kScale);
    }
  }
  float s[8][4];
  #pragma unroll
  for (int nt = 0; nt < 8; nt++) {
    s[nt][0] = s[nt][1] = s[nt][2] = s[nt][3] = 0.f;
    uint32_t bb[4];
    ldm4(bb, swz(uK, 64 * wi + nt * 8 + b2N, h * 32 + b2K));
    mma16816(s[nt], aQ[0], bb);
    mma16816(s[nt], aQ[1], bb + 2);
  }
  float mx0 = -1e30f, mx1 = -1e30f;
  #pragma unroll
  for (int nt = 0; nt < 8; nt++) {
    mx0 = fmaxf(mx0, fmaxf(s[nt][0], s[nt][1]));
    mx1 = fmaxf(mx1, fmaxf(s[nt][2], s[nt][3]));
  }
  mx0 = fmaxf(mx0, __shfl_xor_sync(~0u, mx0, 1)); mx0 = fmaxf(mx0, __shfl_xor_sync(~0u, mx0, 2));
  mx1 = fmaxf(mx1, __shfl_xor_sync(~0u, mx1, 1)); mx1 = fmaxf(mx1, __shfl_xor_sync(~0u, mx1, 2));
  float sm0 = 0.f, sm1 = 0.f;
  #pragma unroll
  for (int nt = 0; nt < 8; nt++) {
    s[nt][0] = __expf(s[nt][0] - mx0); s[nt][1] = __expf(s[nt][1] - mx0);
    s[nt][2] = __expf(s[nt][2] - mx1); s[nt][3] = __expf(s[nt][3] - mx1);
    sm0 += s[nt][0] + s[nt][1]; sm1 += s[nt][2] + s[nt][3];
  }
  sm0 += __shfl_xor_sync(~0u, sm0, 1); sm0 += __shfl_xor_sync(~0u, sm0, 2);
  sm1 += __shfl_xor_sync(~0u, sm1, 1); sm1 += __shfl_xor_sync(~0u, sm1, 2);
  float r0 = __frcp_rn(sm0), r1 = __frcp_rn(sm1);
  uint32_t aP[4][4];
  #pragma unroll
  for (int kt = 0; kt < 4; kt++) {
    aP[kt][0] = packbf(s[2 * kt][0] * r0, s[2 * kt][1] * r0);
    aP[kt][1] = packbf(s[2 * kt][2] * r1, s[2 * kt][3] * r1);
    aP[kt][2] = packbf(s[2 * kt + 1][0] * r0, s[2 * kt + 1][1] * r0);
    aP[kt][3] = packbf(s[2 * kt + 1][2] * r1, s[2 * kt + 1][3] * r1);
  }
  float o[4][4] = {};
  #pragma unroll
  for (int ks = 0; ks < 4; ks++) {
    uint32_t bb0[4], bb1[4];
    ldm4t(bb0, swz(uV, 64 * wi + ks * 16 + tK, h * 32 + tN));
    ldm4t(bb1, swz(uV, 64 * wi + ks * 16 + tK, h * 32 + 16 + tN));
    mma16816(o[0], aP[ks], bb0); mma16816(o[1], aP[ks], bb0 + 2);
    mma16816(o[2], aP[ks], bb1); mma16816(o[3], aP[ks], bb1 + 2);
  }
  __nv_bfloat16* dst = gO + (size_t)lr * kC + h * 32;
  #pragma unroll
  for (int nt = 0; nt < 4; nt++) {
    int col = nt * 8 + tig * 2;
    *(uint32_t*)(dst + (size_t)g * kC + col)       = packbf(o[nt][0], o[nt][1]);
    *(uint32_t*)(dst + (size_t)(8 + g) * kC + col) = packbf(o[nt][2], o[nt][3]);
  }
}

// prefetch one 32x256 bf16 weight chunk into swizzled buffer (256 threads)
__device__ __forceinline__ void prefetch_w(uint32_t uWb, const __nv_bfloat16* __restrict__ src,
                                           int tid) {
  #pragma unroll
  for (int j = 0; j < 4; j++) {
    int idx = tid + 256 * j;
    int row = idx >> 5, seg = idx & 31;
    cpa16(uWb + row * 512 + (((seg ^ (row & 7))) << 4), src + row * 256 + seg * 8);
  }
}

// ---------------- K2: fused QKV projection + windowed attention ----------------
__global__ __launch_bounds__(256, 1) void k_fused(const float* __restrict__ bq,
                                                  const float* __restrict__ bk,
                                                  const float* __restrict__ bv) {
  extern __shared__ char smc[];
  const uint32_t uX  = sptr(smc);
  const uint32_t uK  = uX + 65536;
  const uint32_t uV  = uX + 131072;
  const uint32_t uW0 = uX + 196608;
  const uint32_t uW1 = uX + 212992;
  const int tid = threadIdx.x, w = tid >> 5, lane = tid & 31;

  // X tile load (swizzled) via cp.async
  {
    const __nv_bfloat16* gx = g_X + (size_t)blockIdx.x * 128 * kC;
    #pragma unroll
    for (int j = 0; j < 16; j++) {
      int idx = tid + 256 * j;
      int row = idx >> 5, seg = idx & 31;
      cpa16(uX + row * 512 + (((seg ^ (row & 7))) << 4), gx + row * 256 + seg * 8);
    }
  }
  // chunk i source: 0-7 -> Wk, 8-15 -> Wv, 16-23 -> Wq head slices
  prefetch_w(uW0, g_W + kC * kC, tid);          // chunk 0 (Wk chunk 0), same group as X
  cpa_commit();
  prefetch_w(uW1, g_W + kC * kC + 32 * kC, tid); // chunk 1
  cpa_commit();

  __nv_bfloat16* gO = g_O + (size_t)blockIdx.x * 128 * kC;

  #pragma unroll 1
  for (int i = 0; i < 24; i++) {
    if (i >= 22) asm volatile("cp.async.wait_group 0;" ::: "memory");
    else         asm volatile("cp.async.wait_group 1;" ::: "memory");
    __syncthreads();
    uint32_t uWb = (i & 1) ? uW1 : uW0;
    if (i < 8)       proj_chunk(uX, uWb, uK, bk, i,      w, lane);
    else if (i < 16) proj_chunk(uX, uWb, uV, bv, i - 8,  w, lane);
    else             head_attn(uX, uWb, uK, uV, bq, i - 16, w, lane, gO);
    __syncthreads();
    int nx = i + 2;
    if (nx < 24) {
      const __nv_bfloat16* src =
          (nx < 8)  ? (g_W + kC * kC + nx * 32 * kC) :
          (nx < 16) ? (g_W + 2 * kC * kC + (nx - 8) * 32 * kC) :
                      (g_W + (nx - 16) * 32 * kC);
      prefetch_w(uWb, src, tid);
      cpa_commit();
    } else {
      cpa_commit();  // keep group accounting uniform
    }
  }
}

// ---------------- K3: out-projection + inverse scatter + residual ----------------
__global__ __launch_bounds__(512, 1) void k_proj(const float* __restrict__ inpt,
                                                 const int* __restrict__ pn,
                                                 const int* __restrict__ pt,
                                                 const float* __restrict__ bp,
                                                 float* __restrict__ out) {
  extern __shared__ char smc[];
  const uint32_t uA = sptr(smc);
  const uint32_t uB = uA + 65536;
  int* sDest = (int*)(smc + 131072);
  float* sC = (float*)smc;  // reused after MMA (fp32 128x128 = 64KB, swizzled)
  const int tid = threadIdx.x, w = tid >> 5, lane = tid & 31;
  const int g = lane >> 2, tig = lane & 3;
  const int aRow = lane & 15, aCol = (lane >> 4) << 3;
  const int bN = ((lane >> 4) << 3) + (lane & 7), bK = ((lane >> 3) & 1) << 3;
  const int m0 = blockIdx.x * 128, n0 = blockIdx.y * 128;
  {
    const __nv_bfloat16* ga = g_O + (size_t)m0 * kC;
    const __nv_bfloat16* gb = g_W + 3 * kC * kC + (size_t)n0 * kC;
    #pragma unroll
    for (int j = 0; j < 8; j++) {
      int idx = tid + 512 * j;
      int row = idx >> 5, seg = idx & 31;
      uint32_t off = row * 512 + (((seg ^ (row & 7))) << 4);
      cpa16(uA + off, ga + row * 256 + seg * 8);
      cpa16(uB + off, gb + row * 256 + seg * 8);
    }
    cpa_commit();
  }
  if (tid < 128) {
    int m = m0 + tid;
    int ww = m >> 6, l = m & 63;
    int b = ww >> 9, rem = ww & 511;
    int n = (rem >> 6) * 8 + (l >> 3);
    int t = (rem & 63) * 8 + (l & 7);
    sDest[tid] = ((b * 64 + __ldg(pn + b * 64 + n)) * 512 + __ldg(pt + b * 512 + t)) * kC;
  }
  asm volatile("cp.async.wait_group 0;" ::: "memory");
  __syncthreads();

  const int wm = (w & 3) * 32, wn = (w >> 2) * 32;
  float c[2][4][4] = {};
  #pragma unroll
  for (int k0 = 0; k0 < 256; k0 += 16) {
    uint32_t a0[4], a1[4], b0[4], b1[4];
    ldm4(a0, swz(uA, wm + aRow,      k0 + aCol));
    ldm4(a1, swz(uA, wm + 16 + aRow, k0 + aCol));
    ldm4(b0, swz(uB, wn + bN,        k0 + bK));
    ldm4(b1, swz(uB, wn + 16 + bN,   k0 + bK));
    mma16816(c[0][0], a0, b0); mma16816(c[0][1], a0, b0 + 2);
    mma16816(c[0][2], a0, b1); mma16816(c[0][3], a0, b1 + 2);
    mma16816(c[1][0], a1, b0); mma16816(c[1][1], a1, b0 + 2);
    mma16816(c[1][2], a1, b1); mma16816(c[1][3], a1, b1 + 2);
  }
  __syncthreads();  // done reading sA/sB; now restage C (fp32, swizzled rows of 512B)
  #pragma unroll
  for (int mt = 0; mt < 2; mt++) {
    #pragma unroll
    for (int nt = 0; nt < 4; nt++) {
      int col = wn + nt * 8 + tig * 2;              // fp32 column 0..127
      float e0 = __ldg(bp + n0 + col), e1 = __ldg(bp + n0 + col + 1);
      int r0 = wm + mt * 16 + g, r1 = r0 + 8;
      uint32_t o0 = r0 * 512 + ((((col >> 2) ^ (r0 & 7))) << 4) + (col & 3) * 4;
      uint32_t o1 = r1 * 512 + ((((col >> 2) ^ (r1 & 7))) << 4) + (col & 3) * 4;
      *(float2*)((char*)sC + o0) = {c[mt][nt][0] + e0, c[mt][nt][1] + e1};
      *(float2*)((char*)sC + o1) = {c[mt][nt][2] + e0, c[mt][nt][3] + e1};
    }
  }
  __syncthreads();
  // coalesced scatter: one float4 per thread per iter
  #pragma unroll
  for (int j = 0; j < 8; j++) {
    int idx = tid + 512 * j;
    int row = idx >> 5, seg = idx & 31;
    float4 v = *(float4*)((char*)sC + row * 512 + (((seg ^ (row & 7))) << 4));
    size_t d = (size_t)sDest[row] + n0 + seg * 4;
    float4 iv = *(const float4*)(inpt + d);
    v.x += iv.x; v.y += iv.y; v.z += iv.z; v.w += iv.w;
    *(float4*)(out + d) = v;
  }
}

extern "C" void kernel_launch(void* const* d_in, const int* in_sizes, int n_in,
                              void* d_out, int out_size) {
  const float* inpt = (const float*)d_in[0];
  const int*   pn   = (const int*)d_in[1];
  const int*   pt   = (const int*)d_in[2];
  const float* ln_g = (const float*)d_in[3];
  const float* ln_b = (const float*)d_in[4];
  const float* Wq   = (const float*)d_in[5];
  const float* bq   = (const float*)d_in[6];
  const float* Wk   = (const float*)d_in[7];
  const float* bk   = (const float*)d_in[8];
  const float* Wv   = (const float*)d_in[9];
  const float* bv   = (const float*)d_in[10];
  const float* Wp   = (const float*)d_in[11];
  const float* bp   = (const float*)d_in[12];
  float* out = (float*)d_out;
  (void)in_sizes; (void)n_in; (void)out_size;

  const int smem_fused = 229376;           // X+K+V (192K) + 2 weight buffers (32K)
  const int smem_proj  = 131072 + 512;
  cudaFuncSetAttribute(k_fused, cudaFuncAttributeMaxDynamicSharedMemorySize, smem_fused);
  cudaFuncSetAttribute(k_proj,  cudaFuncAttributeMaxDynamicSharedMemorySize, smem_proj);

  k_convert<<<256, 256>>>(Wq, Wk, Wv, Wp);
  k_ln<<<kTokens / 8, 256>>>(inpt, pn, pt, ln_g, ln_b);
  k_fused<<<1024, 256, smem_fused>>>(bq, bk, bv);
  k_proj<<<dim3(1024, 2), 512, smem_proj>>>(inpt, pn, pt, bp, out);
}

// round 5
// speedup vs baseline: 1.1686x; 1.0439x over previous
#include <cuda_runtime.h>
#include <cuda_bf16.h>
#include <cstdint>

namespace {
constexpr int kC = 256;
constexpr float kScale = 0.17677669529663687f;   // 32^-0.5
}

__device__ __nv_bfloat16 g_O[(size_t)2048 * 64 * kC];  // attention output (pre out-proj)
__device__ __nv_bfloat16 g_W[4 * kC * kC];             // Wq, Wk, Wv, Wp bf16

__device__ __forceinline__ uint32_t sptr(const void* p) {
  return (uint32_t)__cvta_generic_to_shared(p);
}
// XOR-swizzled address: rows are 512B (256 bf16). c = bf16 column (multiple of 8).
__device__ __forceinline__ uint32_t swz(uint32_t base, int r, int c) {
  return base + (uint32_t)(r * 512 + ((((c >> 3) ^ (r & 7))) << 4));
}
__device__ __forceinline__ void ldm4(uint32_t r[4], uint32_t a) {
  asm volatile("ldmatrix.sync.aligned.m8n8.x4.shared.b16 {%0,%1,%2,%3}, [%4];"
               : "=r"(r[0]), "=r"(r[1]), "=r"(r[2]), "=r"(r[3]) : "r"(a));
}
__device__ __forceinline__ void ldm4t(uint32_t r[4], uint32_t a) {
  asm volatile("ldmatrix.sync.aligned.m8n8.x4.trans.shared.b16 {%0,%1,%2,%3}, [%4];"
               : "=r"(r[0]), "=r"(r[1]), "=r"(r[2]), "=r"(r[3]) : "r"(a));
}
__device__ __forceinline__ void mma16816(float c[4], const uint32_t a[4], const uint32_t b[2]) {
  asm volatile("mma.sync.aligned.m16n8k16.row.col.f32.bf16.bf16.f32 "
               "{%0,%1,%2,%3}, {%4,%5,%6,%7}, {%8,%9}, {%0,%1,%2,%3};"
               : "+f"(c[0]), "+f"(c[1]), "+f"(c[2]), "+f"(c[3])
               : "r"(a[0]), "r"(a[1]), "r"(a[2]), "r"(a[3]), "r"(b[0]), "r"(b[1]));
}
__device__ __forceinline__ uint32_t packbf(float x, float y) {
  __nv_bfloat162 t = __floats2bfloat162_rn(x, y);
  return reinterpret_cast<uint32_t&>(t);
}
__device__ __forceinline__ void cpa16(uint32_t d, const void* s) {
  asm volatile("cp.async.cg.shared.global [%0], [%1], 16;" :: "r"(d), "l"(s));
}
__device__ __forceinline__ void cpa_commit() {
  asm volatile("cp.async.commit_group;" ::: "memory");
}

// ---------------- K0: weights fp32 -> bf16 ----------------
__global__ void k_convert(const float* __restrict__ Wq, const float* __restrict__ Wk,
                          const float* __restrict__ Wv, const float* __restrict__ Wp) {
  int i = blockIdx.x * blockDim.x + threadIdx.x;
  constexpr int n = kC * kC;
  g_W[i]         = __float2bfloat16(Wq[i]);
  g_W[n + i]     = __float2bfloat16(Wk[i]);
  g_W[2 * n + i] = __float2bfloat16(Wv[i]);
  g_W[3 * n + i] = __float2bfloat16(Wp[i]);
}

// ---------------- K2 helpers ----------------
// project this warp's 16 rows (A in regs) x 32 cols (chunk nc) with weights in uWb
__device__ __forceinline__ void proj_chunk(const uint32_t aF[16][4], uint32_t uWb, uint32_t uOut,
                                           const float* __restrict__ bias, int nc,
                                           int w, int lane) {
  const int g = lane >> 2, tig = lane & 3;
  const int bN = ((lane >> 4) << 3) + (lane & 7), bK = ((lane >> 3) & 1) << 3;
  const int m0 = 16 * w;
  float c[4][4] = {};
  #pragma unroll
  for (int ks = 0; ks < 16; ks++) {
    uint32_t bb0[4], bb1[4];
    ldm4(bb0, swz(uWb, bN,      ks * 16 + bK));
    ldm4(bb1, swz(uWb, 16 + bN, ks * 16 + bK));
    mma16816(c[0], aF[ks], bb0); mma16816(c[1], aF[ks], bb0 + 2);
    mma16816(c[2], aF[ks], bb1); mma16816(c[3], aF[ks], bb1 + 2);
  }
  #pragma unroll
  for (int nt = 0; nt < 4; nt++) {
    int col = nc * 32 + nt * 8;
    float e0 = __ldg(bias + col + tig * 2), e1 = __ldg(bias + col + tig * 2 + 1);
    *(uint32_t*)(__cvta_shared_to_generic(swz(uOut, m0 + g,     col) + tig * 4))
        = packbf(c[nt][0] + e0, c[nt][1] + e1);
    *(uint32_t*)(__cvta_shared_to_generic(swz(uOut, m0 + 8 + g, col) + tig * 4))
        = packbf(c[nt][2] + e0, c[nt][3] + e1);
  }
}

// Q-proj (A in regs) + attention for head h; uWb holds Wq rows [h*32, h*32+32)
__device__ __forceinline__ void head_attn(const uint32_t aF[16][4], uint32_t uWb,
                                          uint32_t uK, uint32_t uV,
                                          const float* __restrict__ bq, int h,
                                          int w, int lane, __nv_bfloat16* __restrict__ gO) {
  const int g = lane >> 2, tig = lane & 3;
  const int bN = ((lane >> 4) << 3) + (lane & 7), bK = ((lane >> 3) & 1) << 3;
  const int b2N = lane & 7, b2K = (lane >> 3) << 3;
  const int tK = (((lane >> 3) & 1) << 3) + (lane & 7), tN = (lane >> 4) << 3;
  const int wi = w >> 2;
  const int lr = 16 * w;

  float qc[4][4] = {};
  #pragma unroll
  for (int ks = 0; ks < 16; ks++) {
    uint32_t bb0[4], bb1[4];
    ldm4(bb0, swz(uWb, bN,      ks * 16 + bK));
    ldm4(bb1, swz(uWb, 16 + bN, ks * 16 + bK));
    mma16816(qc[0], aF[ks], bb0); mma16816(qc[1], aF[ks], bb0 + 2);
    mma16816(qc[2], aF[ks], bb1); mma16816(qc[3], aF[ks], bb1 + 2);
  }
  uint32_t aQ[2][4];
  #pragma unroll
  for (int kt = 0; kt < 2; kt++) {
    #pragma unroll
    for (int j = 0; j < 2; j++) {
      int nt = 2 * kt + j;
      int col = h * 32 + nt * 8 + tig * 2;
      float e0 = __ldg(bq + col), e1 = __ldg(bq + col + 1);
      aQ[kt][2 * j]     = packbf((qc[nt][0] + e0) * kScale, (qc[nt][1] + e1) * kScale);
      aQ[kt][2 * j + 1] = packbf((qc[nt][2] + e0) * kScale, (qc[nt][3] + e1) * kScale);
    }
  }
  float s[8][4];
  #pragma unroll
  for (int nt = 0; nt < 8; nt++) {
    s[nt][0] = s[nt][1] = s[nt][2] = s[nt][3] = 0.f;
    uint32_t bb[4];
    ldm4(bb, swz(uK, 64 * wi + nt * 8 + b2N, h * 32 + b2K));
    mma16816(s[nt], aQ[0], bb);
    mma16816(s[nt], aQ[1], bb + 2);
  }
  float mx0 = -1e30f, mx1 = -1e30f;
  #pragma unroll
  for (int nt = 0; nt < 8; nt++) {
    mx0 = fmaxf(mx0, fmaxf(s[nt][0], s[nt][1]));
    mx1 = fmaxf(mx1, fmaxf(s[nt][2], s[nt][3]));
  }
  mx0 = fmaxf(mx0, __shfl_xor_sync(~0u, mx0, 1)); mx0 = fmaxf(mx0, __shfl_xor_sync(~0u, mx0, 2));
  mx1 = fmaxf(mx1, __shfl_xor_sync(~0u, mx1, 1)); mx1 = fmaxf(mx1, __shfl_xor_sync(~0u, mx1, 2));
  float sm0 = 0.f, sm1 = 0.f;
  #pragma unroll
  for (int nt = 0; nt < 8; nt++) {
    s[nt][0] = __expf(s[nt][0] - mx0); s[nt][1] = __expf(s[nt][1] - mx0);
    s[nt][2] = __expf(s[nt][2] - mx1); s[nt][3] = __expf(s[nt][3] - mx1);
    sm0 += s[nt][0] + s[nt][1]; sm1 += s[nt][2] + s[nt][3];
  }
  sm0 += __shfl_xor_sync(~0u, sm0, 1); sm0 += __shfl_xor_sync(~0u, sm0, 2);
  sm1 += __shfl_xor_sync(~0u, sm1, 1); sm1 += __shfl_xor_sync(~0u, sm1, 2);
  float r0 = __frcp_rn(sm0), r1 = __frcp_rn(sm1);
  uint32_t aP[4][4];
  #pragma unroll
  for (int kt = 0; kt < 4; kt++) {
    aP[kt][0] = packbf(s[2 * kt][0] * r0, s[2 * kt][1] * r0);
    aP[kt][1] = packbf(s[2 * kt][2] * r1, s[2 * kt][3] * r1);
    aP[kt][2] = packbf(s[2 * kt + 1][0] * r0, s[2 * kt + 1][1] * r0);
    aP[kt][3] = packbf(s[2 * kt + 1][2] * r1, s[2 * kt + 1][3] * r1);
  }
  float o[4][4] = {};
  #pragma unroll
  for (int ks = 0; ks < 4; ks++) {
    uint32_t bb0[4], bb1[4];
    ldm4t(bb0, swz(uV, 64 * wi + ks * 16 + tK, h * 32 + tN));
    ldm4t(bb1, swz(uV, 64 * wi + ks * 16 + tK, h * 32 + 16 + tN));
    mma16816(o[0], aP[ks], bb0); mma16816(o[1], aP[ks], bb0 + 2);
    mma16816(o[2], aP[ks], bb1); mma16816(o[3], aP[ks], bb1 + 2);
  }
  __nv_bfloat16* dst = gO + (size_t)lr * kC + h * 32;
  #pragma unroll
  for (int nt = 0; nt < 4; nt++) {
    int col = nt * 8 + tig * 2;
    *(uint32_t*)(dst + (size_t)g * kC + col)       = packbf(o[nt][0], o[nt][1]);
    *(uint32_t*)(dst + (size_t)(8 + g) * kC + col) = packbf(o[nt][2], o[nt][3]);
  }
}

// prefetch one 32x256 bf16 weight chunk into swizzled buffer (256 threads)
__device__ __forceinline__ void prefetch_w(uint32_t uWb, const __nv_bfloat16* __restrict__ src,
                                           int tid) {
  #pragma unroll
  for (int j = 0; j < 4; j++) {
    int idx = tid + 256 * j;
    int row = idx >> 5, seg = idx & 31;
    cpa16(uWb + row * 512 + (((seg ^ (row & 7))) << 4), src + row * 256 + seg * 8);
  }
}

// ---------------- K2: LN + shuffle + QKV projection + windowed attention ----------------
__global__ __launch_bounds__(256, 1) void k_fused(const float* __restrict__ inpt,
                                                  const int* __restrict__ pn,
                                                  const int* __restrict__ pt,
                                                  const float* __restrict__ gam,
                                                  const float* __restrict__ bet,
                                                  const float* __restrict__ bq,
                                                  const float* __restrict__ bk,
                                                  const float* __restrict__ bv) {
  extern __shared__ char smc[];
  const uint32_t uX  = sptr(smc);
  const uint32_t uK  = uX + 65536;
  const uint32_t uV  = uX + 131072;
  const uint32_t uW0 = uX + 196608;
  const uint32_t uW1 = uX + 212992;
  const int tid = threadIdx.x, w = tid >> 5, lane = tid & 31;

  // kick off weight pipeline first
  prefetch_w(uW0, g_W + kC * kC, tid);            // chunk 0 (Wk chunk 0)
  cpa_commit();
  prefetch_w(uW1, g_W + kC * kC + 32 * kC, tid);  // chunk 1
  cpa_commit();

  // ---- LN + gather for this warp's 16 rows ----
  {
    int c0 = lane * 8;
    float4 g0v = *(const float4*)(gam + c0);
    float4 g1v = *(const float4*)(gam + c0 + 4);
    float4 b0v = *(const float4*)(bet + c0);
    float4 b1v = *(const float4*)(bet + c0 + 4);
    const int mBase = blockIdx.x * 128 + 16 * w;
    #pragma unroll 1
    for (int r = 0; r < 16; r++) {
      int m = mBase + r;
      int ww = m >> 6, l = m & 63;
      int b = ww >> 9, rem = ww & 511;
      int n = (rem >> 6) * 8 + (l >> 3);
      int t = (rem & 63) * 8 + (l & 7);
      int sn = __ldg(pn + b * 64 + n);
      int st = __ldg(pt + b * 512 + t);
      const float* src = inpt + ((size_t)((b * 64 + sn) * 512 + st)) * kC + c0;
      float4 p0 = *(const float4*)(src);
      float4 p1 = *(const float4*)(src + 4);
      float s = p0.x + p0.y + p0.z + p0.w + p1.x + p1.y + p1.z + p1.w;
      float ss = p0.x * p0.x + p0.y * p0.y + p0.z * p0.z + p0.w * p0.w
               + p1.x * p1.x + p1.y * p1.y + p1.z * p1.z + p1.w * p1.w;
      #pragma unroll
      for (int o = 16; o; o >>= 1) {
        s  += __shfl_xor_sync(~0u, s,  o);
        ss += __shfl_xor_sync(~0u, ss, o);
      }
      float mean = s * (1.f / 256.f);
      float inv = rsqrtf(ss * (1.f / 256.f) - mean * mean + 1e-5f);
      uint4 rv;
      rv.x = packbf((p0.x - mean) * inv * g0v.x + b0v.x, (p0.y - mean) * inv * g0v.y + b0v.y);
      rv.y = packbf((p0.z - mean) * inv * g0v.z + b0v.z, (p0.w - mean) * inv * g0v.w + b0v.w);
      rv.z = packbf((p1.x - mean) * inv * g1v.x + b1v.x, (p1.y - mean) * inv * g1v.y + b1v.y);
      rv.w = packbf((p1.z - mean) * inv * g1v.z + b1v.z, (p1.w - mean) * inv * g1v.w + b1v.w);
      *(uint4*)(__cvta_shared_to_generic(swz(uX, 16 * w + r, c0))) = rv;
    }
  }
  __syncwarp();
  // ---- extract this warp's A fragments once ----
  uint32_t aF[16][4];
  {
    const int aRow = lane & 15, aCol = (lane >> 4) << 3;
    #pragma unroll
    for (int ks = 0; ks < 16; ks++)
      ldm4(aF[ks], swz(uX, 16 * w + aRow, ks * 16 + aCol));
  }

  __nv_bfloat16* gO = g_O + (size_t)blockIdx.x * 128 * kC;

  // chunk i: 0-7 -> Wk, 8-15 -> Wv, 16-23 -> Wq head slices
  #pragma unroll 1
  for (int i = 0; i < 24; i++) {
    if (i >= 22) asm volatile("cp.async.wait_group 0;" ::: "memory");
    else         asm volatile("cp.async.wait_group 1;" ::: "memory");
    __syncthreads();
    uint32_t uWb = (i & 1) ? uW1 : uW0;
    if (i < 8)       proj_chunk(aF, uWb, uK, bk, i,      w, lane);
    else if (i < 16) proj_chunk(aF, uWb, uV, bv, i - 8,  w, lane);
    else             head_attn(aF, uWb, uK, uV, bq, i - 16, w, lane, gO);
    __syncthreads();
    int nx = i + 2;
    if (nx < 24) {
      const __nv_bfloat16* src =
          (nx < 8)  ? (g_W + kC * kC + nx * 32 * kC) :
          (nx < 16) ? (g_W + 2 * kC * kC + (nx - 8) * 32 * kC) :
                      (g_W + (nx - 16) * 32 * kC);
      prefetch_w(uWb, src, tid);
      cpa_commit();
    } else {
      cpa_commit();
    }
  }
}

// ---------------- K3: out-projection + inverse scatter + residual ----------------
// 64x128 tiles, 256 threads, ~96KB smem -> 2 CTAs/SM
__global__ __launch_bounds__(256, 2) void k_proj(const float* __restrict__ inpt,
                                                 const int* __restrict__ pn,
                                                 const int* __restrict__ pt,
                                                 const float* __restrict__ bp,
                                                 float* __restrict__ out) {
  extern __shared__ char smc[];
  const uint32_t uA = sptr(smc);
  const uint32_t uB = uA + 32768;
  int* sDest = (int*)(smc + 98304);
  float* sC = (float*)smc;  // reuse A region after MMA (64x128 fp32 = 32KB)
  const int tid = threadIdx.x, w = tid >> 5, lane = tid & 31;
  const int g = lane >> 2, tig = lane & 3;
  const int aRow = lane & 15, aCol = (lane >> 4) << 3;
  const int bN = ((lane >> 4) << 3) + (lane & 7), bK = ((lane >> 3) & 1) << 3;
  const int m0 = blockIdx.x * 64, n0 = blockIdx.y * 128;
  {
    const __nv_bfloat16* ga = g_O + (size_t)m0 * kC;
    const __nv_bfloat16* gb = g_W + 3 * kC * kC + (size_t)n0 * kC;
    #pragma unroll
    for (int j = 0; j < 8; j++) {
      int idx = tid + 256 * j;
      int row = idx >> 5, seg = idx & 31;
      uint32_t off = row * 512 + (((seg ^ (row & 7))) << 4);
      cpa16(uA + off, ga + row * 256 + seg * 8);
    }
    #pragma unroll
    for (int j = 0; j < 16; j++) {
      int idx = tid + 256 * j;
      int row = idx >> 5, seg = idx & 31;
      uint32_t off = row * 512 + (((seg ^ (row & 7))) << 4);
      cpa16(uB + off, gb + row * 256 + seg * 8);
    }
    cpa_commit();
  }
  if (tid < 64) {
    int m = m0 + tid;
    int ww = m >> 6, l = m & 63;
    int b = ww >> 9, rem = ww & 511;
    int n = (rem >> 6) * 8 + (l >> 3);
    int t = (rem & 63) * 8 + (l & 7);
    sDest[tid] = ((b * 64 + __ldg(pn + b * 64 + n)) * 512 + __ldg(pt + b * 512 + t)) * kC;
  }
  asm volatile("cp.async.wait_group 0;" ::: "memory");
  __syncthreads();

  // warp tile: 32 rows x 32 cols (2m x 4n layout)
  const int wm = (w & 1) * 32, wn = (w >> 1) * 32;
  float c[2][4][4] = {};
  #pragma unroll
  for (int k0 = 0; k0 < 256; k0 += 16) {
    uint32_t a0[4], a1[4], b0[4], b1[4];
    ldm4(a0, swz(uA, wm + aRow,      k0 + aCol));
    ldm4(a1, swz(uA, wm + 16 + aRow, k0 + aCol));
    ldm4(b0, swz(uB, wn + bN,        k0 + bK));
    ldm4(b1, swz(uB, wn + 16 + bN,   k0 + bK));
    mma16816(c[0][0], a0, b0); mma16816(c[0][1], a0, b0 + 2);
    mma16816(c[0][2], a0, b1); mma16816(c[0][3], a0, b1 + 2);
    mma16816(c[1][0], a1, b0); mma16816(c[1][1], a1, b0 + 2);
    mma16816(c[1][2], a1, b1); mma16816(c[1][3], a1, b1 + 2);
  }
  __syncthreads();  // done reading sA; restage C into fp32 swizzled rows (512B)
  #pragma unroll
  for (int mt = 0; mt < 2; mt++) {
    #pragma unroll
    for (int nt = 0; nt < 4; nt++) {
      int col = wn + nt * 8 + tig * 2;   // fp32 column 0..127
      float e0 = __ldg(bp + n0 + col), e1 = __ldg(bp + n0 + col + 1);
      int r0 = wm + mt * 16 + g, r1 = r0 + 8;
      uint32_t o0 = r0 * 512 + ((((col >> 2) ^ (r0 & 7))) << 4) + (col & 3) * 4;
      uint32_t o1 = r1 * 512 + ((((col >> 2) ^ (r1 & 7))) << 4) + (col & 3) * 4;
      *(float2*)((char*)sC + o0) = {c[mt][nt][0] + e0, c[mt][nt][1] + e1};
      *(float2*)((char*)sC + o1) = {c[mt][nt][2] + e0, c[mt][nt][3] + e1};
    }
  }
  __syncthreads();
  // coalesced residual + scatter: one float4 per thread per iter
  #pragma unroll
  for (int j = 0; j < 8; j++) {
    int idx = tid + 256 * j;
    int row = idx >> 5, seg = idx & 31;
    float4 v = *(float4*)((char*)sC + row * 512 + (((seg ^ (row & 7))) << 4));
    size_t d = (size_t)sDest[row] + n0 + seg * 4;
    float4 iv = *(const float4*)(inpt + d);
    v.x += iv.x; v.y += iv.y; v.z += iv.z; v.w += iv.w;
    *(float4*)(out + d) = v;
  }
}

extern "C" void kernel_launch(void* const* d_in, const int* in_sizes, int n_in,
                              void* d_out, int out_size) {
  const float* inpt = (const float*)d_in[0];
  const int*   pn   = (const int*)d_in[1];
  const int*   pt   = (const int*)d_in[2];
  const float* ln_g = (const float*)d_in[3];
  const float* ln_b = (const float*)d_in[4];
  const float* Wq   = (const float*)d_in[5];
  const float* bq   = (const float*)d_in[6];
  const float* Wk   = (const float*)d_in[7];
  const float* bk   = (const float*)d_in[8];
  const float* Wv   = (const float*)d_in[9];
  const float* bv   = (const float*)d_in[10];
  const float* Wp   = (const float*)d_in[11];
  const float* bp   = (const float*)d_in[12];
  float* out = (float*)d_out;
  (void)in_sizes; (void)n_in; (void)out_size;

  const int smem_fused = 229376;           // X+K+V (192K) + 2 weight buffers (32K)
  const int smem_proj  = 98304 + 256;      // A 32K + B 64K + sDest
  cudaFuncSetAttribute(k_fused, cudaFuncAttributeMaxDynamicSharedMemorySize, smem_fused);
  cudaFuncSetAttribute(k_proj,  cudaFuncAttributeMaxDynamicSharedMemorySize, smem_proj);

  k_convert<<<256, 256>>>(Wq, Wk, Wv, Wp);
  k_fused<<<1024, 256, smem_fused>>>(inpt, pn, pt, ln_g, ln_b, bq, bk, bv);
  k_proj<<<dim3(2048, 2), 256, smem_proj>>>(inpt, pn, pt, bp, out);
}

// round 6
// speedup vs baseline: 1.3149x; 1.1252x over previous
#include <cuda_runtime.h>
#include <cuda_bf16.h>
#include <cstdint>

namespace {
constexpr int kC = 256;
constexpr float kScale = 0.17677669529663687f;   // 32^-0.5
}

__device__ __nv_bfloat16 g_O[(size_t)2048 * 64 * kC];  // attention output (pre out-proj)
__device__ __nv_bfloat16 g_W[4 * kC * kC];             // Wq, Wk, Wv, Wp bf16

__device__ __forceinline__ uint32_t sptr(const void* p) {
  return (uint32_t)__cvta_generic_to_shared(p);
}
// XOR-swizzled address: rows are 512B (256 bf16). c = bf16 column (multiple of 8).
__device__ __forceinline__ uint32_t swz(uint32_t base, int r, int c) {
  return base + (uint32_t)(r * 512 + ((((c >> 3) ^ (r & 7))) << 4));
}
__device__ __forceinline__ void ldm4(uint32_t r[4], uint32_t a) {
  asm volatile("ldmatrix.sync.aligned.m8n8.x4.shared.b16 {%0,%1,%2,%3}, [%4];"
               : "=r"(r[0]), "=r"(r[1]), "=r"(r[2]), "=r"(r[3]) : "r"(a));
}
__device__ __forceinline__ void ldm4t(uint32_t r[4], uint32_t a) {
  asm volatile("ldmatrix.sync.aligned.m8n8.x4.trans.shared.b16 {%0,%1,%2,%3}, [%4];"
               : "=r"(r[0]), "=r"(r[1]), "=r"(r[2]), "=r"(r[3]) : "r"(a));
}
__device__ __forceinline__ void mma16816(float c[4], const uint32_t a[4], const uint32_t b[2]) {
  asm volatile("mma.sync.aligned.m16n8k16.row.col.f32.bf16.bf16.f32 "
               "{%0,%1,%2,%3}, {%4,%5,%6,%7}, {%8,%9}, {%0,%1,%2,%3};"
               : "+f"(c[0]), "+f"(c[1]), "+f"(c[2]), "+f"(c[3])
               : "r"(a[0]), "r"(a[1]), "r"(a[2]), "r"(a[3]), "r"(b[0]), "r"(b[1]));
}
__device__ __forceinline__ uint32_t packbf(float x, float y) {
  __nv_bfloat162 t = __floats2bfloat162_rn(x, y);
  return reinterpret_cast<uint32_t&>(t);
}
__device__ __forceinline__ void cpa16(uint32_t d, const void* s) {
  asm volatile("cp.async.cg.shared.global [%0], [%1], 16;" :: "r"(d), "l"(s));
}
__device__ __forceinline__ void cpa_commit() {
  asm volatile("cp.async.commit_group;" ::: "memory");
}

// ---------------- K0: weights fp32 -> bf16 ----------------
__global__ void k_convert(const float* __restrict__ Wq, const float* __restrict__ Wk,
                          const float* __restrict__ Wv, const float* __restrict__ Wp) {
  int i = blockIdx.x * blockDim.x + threadIdx.x;
  constexpr int n = kC * kC;
  g_W[i]         = __float2bfloat16(Wq[i]);
  g_W[n + i]     = __float2bfloat16(Wk[i]);
  g_W[2 * n + i] = __float2bfloat16(Wv[i]);
  g_W[3 * n + i] = __float2bfloat16(Wp[i]);
}

// ---------------- K2 helpers ----------------
// warp computes its 16 rows (A in regs) x 32 cols (col-half ch of 64-col chunk nc)
__device__ __forceinline__ void proj_chunk64(const uint32_t aF[16][4], uint32_t uWb, uint32_t uOut,
                                             const float* __restrict__ bias, int nc,
                                             int rg, int ch, int lane) {
  const int g = lane >> 2, tig = lane & 3;
  const int bN = ((lane >> 4) << 3) + (lane & 7), bK = ((lane >> 3) & 1) << 3;
  const int cb = ch * 32;            // base row in weight buffer
  const int m0 = 16 * rg;
  float c[4][4] = {};
  #pragma unroll
  for (int ks = 0; ks < 16; ks++) {
    uint32_t bb0[4], bb1[4];
    ldm4(bb0, swz(uWb, cb + bN,      ks * 16 + bK));
    ldm4(bb1, swz(uWb, cb + 16 + bN, ks * 16 + bK));
    mma16816(c[0], aF[ks], bb0); mma16816(c[1], aF[ks], bb0 + 2);
    mma16816(c[2], aF[ks], bb1); mma16816(c[3], aF[ks], bb1 + 2);
  }
  #pragma unroll
  for (int nt = 0; nt < 4; nt++) {
    int col = nc * 64 + ch * 32 + nt * 8;
    float e0 = __ldg(bias + col + tig * 2), e1 = __ldg(bias + col + tig * 2 + 1);
    *(uint32_t*)(__cvta_shared_to_generic(swz(uOut, m0 + g,     col) + tig * 4))
        = packbf(c[nt][0] + e0, c[nt][1] + e1);
    *(uint32_t*)(__cvta_shared_to_generic(swz(uOut, m0 + 8 + g, col) + tig * 4))
        = packbf(c[nt][2] + e0, c[nt][3] + e1);
  }
}

// Q-proj (A in regs) + attention. uWb holds Wq rows [hp*64, hp*64+64); warp takes head hp*2+ch.
__device__ __forceinline__ void head_attn64(const uint32_t aF[16][4], uint32_t uWb,
                                            uint32_t uK, uint32_t uV,
                                            const float* __restrict__ bq, int hp,
                                            int rg, int ch, int lane,
                                            __nv_bfloat16* __restrict__ gO) {
  const int g = lane >> 2, tig = lane & 3;
  const int bN = ((lane >> 4) << 3) + (lane & 7), bK = ((lane >> 3) & 1) << 3;
  const int b2N = lane & 7, b2K = (lane >> 3) << 3;
  const int tK = (((lane >> 3) & 1) << 3) + (lane & 7), tN = (lane >> 4) << 3;
  const int h = hp * 2 + ch;         // this warp's head
  const int cb = ch * 32;            // head's rows within weight buffer
  const int wi = rg >> 2;            // window
  const int lr = 16 * rg;

  float qc[4][4] = {};
  #pragma unroll
  for (int ks = 0; ks < 16; ks++) {
    uint32_t bb0[4], bb1[4];
    ldm4(bb0, swz(uWb, cb + bN,      ks * 16 + bK));
    ldm4(bb1, swz(uWb, cb + 16 + bN, ks * 16 + bK));
    mma16816(qc[0], aF[ks], bb0); mma16816(qc[1], aF[ks], bb0 + 2);
    mma16816(qc[2], aF[ks], bb1); mma16816(qc[3], aF[ks], bb1 + 2);
  }
  uint32_t aQ[2][4];
  #pragma unroll
  for (int kt = 0; kt < 2; kt++) {
    #pragma unroll
    for (int j = 0; j < 2; j++) {
      int nt = 2 * kt + j;
      int col = h * 32 + nt * 8 + tig * 2;
      float e0 = __ldg(bq + col), e1 = __ldg(bq + col + 1);
      aQ[kt][2 * j]     = packbf((qc[nt][0] + e0) * kScale, (qc[nt][1] + e1) * kScale);
      aQ[kt][2 * j + 1] = packbf((qc[nt][2] + e0) * kScale, (qc[nt][3] + e1) * kScale);
    }
  }
  float s[8][4];
  #pragma unroll
  for (int nt = 0; nt < 8; nt++) {
    s[nt][0] = s[nt][1] = s[nt][2] = s[nt][3] = 0.f;
    uint32_t bb[4];
    ldm4(bb, swz(uK, 64 * wi + nt * 8 + b2N, h * 32 + b2K));
    mma16816(s[nt], aQ[0], bb);
    mma16816(s[nt], aQ[1], bb + 2);
  }
  float mx0 = -1e30f, mx1 = -1e30f;
  #pragma unroll
  for (int nt = 0; nt < 8; nt++) {
    mx0 = fmaxf(mx0, fmaxf(s[nt][0], s[nt][1]));
    mx1 = fmaxf(mx1, fmaxf(s[nt][2], s[nt][3]));
  }
  mx0 = fmaxf(mx0, __shfl_xor_sync(~0u, mx0, 1)); mx0 = fmaxf(mx0, __shfl_xor_sync(~0u, mx0, 2));
  mx1 = fmaxf(mx1, __shfl_xor_sync(~0u, mx1, 1)); mx1 = fmaxf(mx1, __shfl_xor_sync(~0u, mx1, 2));
  float sm0 = 0.f, sm1 = 0.f;
  #pragma unroll
  for (int nt = 0; nt < 8; nt++) {
    s[nt][0] = __expf(s[nt][0] - mx0); s[nt][1] = __expf(s[nt][1] - mx0);
    s[nt][2] = __expf(s[nt][2] - mx1); s[nt][3] = __expf(s[nt][3] - mx1);
    sm0 += s[nt][0] + s[nt][1]; sm1 += s[nt][2] + s[nt][3];
  }
  sm0 += __shfl_xor_sync(~0u, sm0, 1); sm0 += __shfl_xor_sync(~0u, sm0, 2);
  sm1 += __shfl_xor_sync(~0u, sm1, 1); sm1 += __shfl_xor_sync(~0u, sm1, 2);
  float r0 = __frcp_rn(sm0), r1 = __frcp_rn(sm1);
  uint32_t aP[4][4];
  #pragma unroll
  for (int kt = 0; kt < 4; kt++) {
    aP[kt][0] = packbf(s[2 * kt][0] * r0, s[2 * kt][1] * r0);
    aP[kt][1] = packbf(s[2 * kt][2] * r1, s[2 * kt][3] * r1);
    aP[kt][2] = packbf(s[2 * kt + 1][0] * r0, s[2 * kt + 1][1] * r0);
    aP[kt][3] = packbf(s[2 * kt + 1][2] * r1, s[2 * kt + 1][3] * r1);
  }
  float o[4][4] = {};
  #pragma unroll
  for (int ks = 0; ks < 4; ks++) {
    uint32_t bb0[4], bb1[4];
    ldm4t(bb0, swz(uV, 64 * wi + ks * 16 + tK, h * 32 + tN));
    ldm4t(bb1, swz(uV, 64 * wi + ks * 16 + tK, h * 32 + 16 + tN));
    mma16816(o[0], aP[ks], bb0); mma16816(o[1], aP[ks], bb0 + 2);
    mma16816(o[2], aP[ks], bb1); mma16816(o[3], aP[ks], bb1 + 2);
  }
  __nv_bfloat16* dst = gO + (size_t)lr * kC + h * 32;
  #pragma unroll
  for (int nt = 0; nt < 4; nt++) {
    int col = nt * 8 + tig * 2;
    *(uint32_t*)(dst + (size_t)g * kC + col)       = packbf(o[nt][0], o[nt][1]);
    *(uint32_t*)(dst + (size_t)(8 + g) * kC + col) = packbf(o[nt][2], o[nt][3]);
  }
}

// prefetch one 64x256 bf16 weight chunk (32KB) into swizzled buffer (512 threads)
__device__ __forceinline__ void prefetch_w64(uint32_t uWb, const __nv_bfloat16* __restrict__ src,
                                             int tid) {
  #pragma unroll
  for (int j = 0; j < 4; j++) {
    int idx = tid + 512 * j;
    int row = idx >> 5, seg = idx & 31;
    cpa16(uWb + row * 512 + (((seg ^ (row & 7))) << 4), src + row * 256 + seg * 8);
  }
}

// ---------------- K2: LN + shuffle + QKV projection + windowed attention ----------------
// 512 threads; warp = (row-group rg = w>>1 of 16 rows, col-half ch = w&1)
__global__ __launch_bounds__(512, 1) void k_fused(const float* __restrict__ inpt,
                                                  const int* __restrict__ pn,
                                                  const int* __restrict__ pt,
                                                  const float* __restrict__ gam,
                                                  const float* __restrict__ bet,
                                                  const float* __restrict__ bq,
                                                  const float* __restrict__ bk,
                                                  const float* __restrict__ bv) {
  extern __shared__ char smc[];
  const uint32_t uK  = sptr(smc);            // 64KB: X staging, then projected K
  const uint32_t uV  = uK + 65536;           // 64KB: projected V
  const uint32_t uW0 = uK + 131072;          // 32KB weight buffer
  const uint32_t uW1 = uK + 163840;          // 32KB weight buffer
  const int tid = threadIdx.x, w = tid >> 5, lane = tid & 31;
  const int rg = w >> 1, ch = w & 1;

  // weight pipeline starts immediately (overlaps LN/gather)
  prefetch_w64(uW0, g_W + kC * kC, tid);            // chunk 0 = Wk cols 0..63
  cpa_commit();
  prefetch_w64(uW1, g_W + kC * kC + 64 * kC, tid);  // chunk 1 = Wk cols 64..127
  cpa_commit();

  // ---- LN + gather: warp w handles rows [8w, 8w+8), staged into uK region ----
  {
    int c0 = lane * 8;
    float4 g0v = *(const float4*)(gam + c0);
    float4 g1v = *(const float4*)(gam + c0 + 4);
    float4 b0v = *(const float4*)(bet + c0);
    float4 b1v = *(const float4*)(bet + c0 + 4);
    const int mBase = blockIdx.x * 128 + 8 * w;
    #pragma unroll 1
    for (int rp = 0; rp < 4; rp++) {
      // two rows per step for MLP
      float4 pa0, pa1, pb0, pb1;
      int rowA = 8 * w + 2 * rp, rowB = rowA + 1;
      {
        int m = mBase + 2 * rp;
        int ww = m >> 6, l = m & 63;
        int b = ww >> 9, rem = ww & 511;
        int n = (rem >> 6) * 8 + (l >> 3);
        int t = (rem & 63) * 8 + (l & 7);
        const float* src = inpt + ((size_t)((b * 64 + __ldg(pn + b * 64 + n)) * 512
                                            + __ldg(pt + b * 512 + t))) * kC + c0;
        pa0 = *(const float4*)(src);
        pa1 = *(const float4*)(src + 4);
      }
      {
        int m = mBase + 2 * rp + 1;
        int ww = m >> 6, l = m & 63;
        int b = ww >> 9, rem = ww & 511;
        int n = (rem >> 6) * 8 + (l >> 3);
        int t = (rem & 63) * 8 + (l & 7);
        const float* src = inpt + ((size_t)((b * 64 + __ldg(pn + b * 64 + n)) * 512
                                            + __ldg(pt + b * 512 + t))) * kC + c0;
        pb0 = *(const float4*)(src);
        pb1 = *(const float4*)(src + 4);
      }
      float sA = pa0.x + pa0.y + pa0.z + pa0.w + pa1.x + pa1.y + pa1.z + pa1.w;
      float qA = pa0.x * pa0.x + pa0.y * pa0.y + pa0.z * pa0.z + pa0.w * pa0.w
               + pa1.x * pa1.x + pa1.y * pa1.y + pa1.z * pa1.z + pa1.w * pa1.w;
      float sB = pb0.x + pb0.y + pb0.z + pb0.w + pb1.x + pb1.y + pb1.z + pb1.w;
      float qB = pb0.x * pb0.x + pb0.y * pb0.y + pb0.z * pb0.z + pb0.w * pb0.w
               + pb1.x * pb1.x + pb1.y * pb1.y + pb1.z * pb1.z + pb1.w * pb1.w;
      #pragma unroll
      for (int o = 16; o; o >>= 1) {
        sA += __shfl_xor_sync(~0u, sA, o);
        qA += __shfl_xor_sync(~0u, qA, o);
        sB += __shfl_xor_sync(~0u, sB, o);
        qB += __shfl_xor_sync(~0u, qB, o);
      }
      float mA = sA * (1.f / 256.f), mB = sB * (1.f / 256.f);
      float iA = rsqrtf(qA * (1.f / 256.f) - mA * mA + 1e-5f);
      float iB = rsqrtf(qB * (1.f / 256.f) - mB * mB + 1e-5f);
      uint4 rv;
      rv.x = packbf((pa0.x - mA) * iA * g0v.x + b0v.x, (pa0.y - mA) * iA * g0v.y + b0v.y);
      rv.y = packbf((pa0.z - mA) * iA * g0v.z + b0v.z, (pa0.w - mA) * iA * g0v.w + b0v.w);
      rv.z = packbf((pa1.x - mA) * iA * g1v.x + b1v.x, (pa1.y - mA) * iA * g1v.y + b1v.y);
      rv.w = packbf((pa1.z - mA) * iA * g1v.z + b1v.z, (pa1.w - mA) * iA * g1v.w + b1v.w);
      *(uint4*)(__cvta_shared_to_generic(swz(uK, rowA, c0))) = rv;
      rv.x = packbf((pb0.x - mB) * iB * g0v.x + b0v.x, (pb0.y - mB) * iB * g0v.y + b0v.y);
      rv.y = packbf((pb0.z - mB) * iB * g0v.z + b0v.z, (pb0.w - mB) * iB * g0v.w + b0v.w);
      rv.z = packbf((pb1.x - mB) * iB * g1v.x + b1v.x, (pb1.y - mB) * iB * g1v.y + b1v.y);
      rv.w = packbf((pb1.z - mB) * iB * g1v.z + b1v.z, (pb1.w - mB) * iB * g1v.w + b1v.w);
      *(uint4*)(__cvta_shared_to_generic(swz(uK, rowB, c0))) = rv;
    }
  }
  __syncthreads();
  // ---- extract this warp's A fragments once (X lives in uK region transiently) ----
  uint32_t aF[16][4];
  {
    const int aRow = lane & 15, aCol = (lane >> 4) << 3;
    #pragma unroll
    for (int ks = 0; ks < 16; ks++)
      ldm4(aF[ks], swz(uK, 16 * rg + aRow, ks * 16 + aCol));
  }
  __syncthreads();  // all extractions done before uK is overwritten with projected K

  __nv_bfloat16* gO = g_O + (size_t)blockIdx.x * 128 * kC;

  // chunk i: 0-3 -> Wk (64 cols each), 4-7 -> Wv, 8-11 -> Wq head pairs
  #pragma unroll 1
  for (int i = 0; i < 12; i++) {
    asm volatile("cp.async.wait_group 1;" ::: "memory");
    __syncthreads();
    uint32_t uWb = (i & 1) ? uW1 : uW0;
    if (i < 4)      proj_chunk64(aF, uWb, uK, bk, i,     rg, ch, lane);
    else if (i < 8) proj_chunk64(aF, uWb, uV, bv, i - 4, rg, ch, lane);
    else            head_attn64(aF, uWb, uK, uV, bq, i - 8, rg, ch, lane, gO);
    __syncthreads();
    int nx = i + 2;
    if (nx < 12) {
      const __nv_bfloat16* src =
          (nx < 4) ? (g_W + kC * kC + nx * 64 * kC) :
          (nx < 8) ? (g_W + 2 * kC * kC + (nx - 4) * 64 * kC) :
                     (g_W + (nx - 8) * 64 * kC);
      prefetch_w64(uWb, src, tid);
    }
    cpa_commit();
  }
}

// ---------------- K3: out-projection + inverse scatter + residual ----------------
// 64x128 tiles, 256 threads, ~96KB smem -> 2 CTAs/SM
__global__ __launch_bounds__(256, 2) void k_proj(const float* __restrict__ inpt,
                                                 const int* __restrict__ pn,
                                                 const int* __restrict__ pt,
                                                 const float* __restrict__ bp,
                                                 float* __restrict__ out) {
  extern __shared__ char smc[];
  const uint32_t uA = sptr(smc);
  const uint32_t uB = uA + 32768;
  int* sDest = (int*)(smc + 98304);
  float* sC = (float*)smc;  // reuse A region after MMA (64x128 fp32 = 32KB)
  const int tid = threadIdx.x, w = tid >> 5, lane = tid & 31;
  const int g = lane >> 2, tig = lane & 3;
  const int aRow = lane & 15, aCol = (lane >> 4) << 3;
  const int bN = ((lane >> 4) << 3) + (lane & 7), bK = ((lane >> 3) & 1) << 3;
  const int m0 = blockIdx.x * 64, n0 = blockIdx.y * 128;
  {
    const __nv_bfloat16* ga = g_O + (size_t)m0 * kC;
    const __nv_bfloat16* gb = g_W + 3 * kC * kC + (size_t)n0 * kC;
    #pragma unroll
    for (int j = 0; j < 8; j++) {
      int idx = tid + 256 * j;
      int row = idx >> 5, seg = idx & 31;
      uint32_t off = row * 512 + (((seg ^ (row & 7))) << 4);
      cpa16(uA + off, ga + row * 256 + seg * 8);
    }
    #pragma unroll
    for (int j = 0; j < 16; j++) {
      int idx = tid + 256 * j;
      int row = idx >> 5, seg = idx & 31;
      uint32_t off = row * 512 + (((seg ^ (row & 7))) << 4);
      cpa16(uB + off, gb + row * 256 + seg * 8);
    }
    cpa_commit();
  }
  if (tid < 64) {
    int m = m0 + tid;
    int ww = m >> 6, l = m & 63;
    int b = ww >> 9, rem = ww & 511;
    int n = (rem >> 6) * 8 + (l >> 3);
    int t = (rem & 63) * 8 + (l & 7);
    sDest[tid] = ((b * 64 + __ldg(pn + b * 64 + n)) * 512 + __ldg(pt + b * 512 + t)) * kC;
  }
  asm volatile("cp.async.wait_group 0;" ::: "memory");
  __syncthreads();

  const int wm = (w & 1) * 32, wn = (w >> 1) * 32;
  float c[2][4][4] = {};
  #pragma unroll
  for (int k0 = 0; k0 < 256; k0 += 16) {
    uint32_t a0[4], a1[4], b0[4], b1[4];
    ldm4(a0, swz(uA, wm + aRow,      k0 + aCol));
    ldm4(a1, swz(uA, wm + 16 + aRow, k0 + aCol));
    ldm4(b0, swz(uB, wn + bN,        k0 + bK));
    ldm4(b1, swz(uB, wn + 16 + bN,   k0 + bK));
    mma16816(c[0][0], a0, b0); mma16816(c[0][1], a0, b0 + 2);
    mma16816(c[0][2], a0, b1); mma16816(c[0][3], a0, b1 + 2);
    mma16816(c[1][0], a1, b0); mma16816(c[1][1], a1, b0 + 2);
    mma16816(c[1][2], a1, b1); mma16816(c[1][3], a1, b1 + 2);
  }
  __syncthreads();
  #pragma unroll
  for (int mt = 0; mt < 2; mt++) {
    #pragma unroll
    for (int nt = 0; nt < 4; nt++) {
      int col = wn + nt * 8 + tig * 2;
      float e0 = __ldg(bp + n0 + col), e1 = __ldg(bp + n0 + col + 1);
      int r0 = wm + mt * 16 + g, r1 = r0 + 8;
      uint32_t o0 = r0 * 512 + ((((col >> 2) ^ (r0 & 7))) << 4) + (col & 3) * 4;
      uint32_t o1 = r1 * 512 + ((((col >> 2) ^ (r1 & 7))) << 4) + (col & 3) * 4;
      *(float2*)((char*)sC + o0) = {c[mt][nt][0] + e0, c[mt][nt][1] + e1};
      *(float2*)((char*)sC + o1) = {c[mt][nt][2] + e0, c[mt][nt][3] + e1};
    }
  }
  __syncthreads();
  #pragma unroll
  for (int j = 0; j < 8; j++) {
    int idx = tid + 256 * j;
    int row = idx >> 5, seg = idx & 31;
    float4 v = *(float4*)((char*)sC + row * 512 + (((seg ^ (row & 7))) << 4));
    size_t d = (size_t)sDest[row] + n0 + seg * 4;
    float4 iv = *(const float4*)(inpt + d);
    v.x += iv.x; v.y += iv.y; v.z += iv.z; v.w += iv.w;
    *(float4*)(out + d) = v;
  }
}

extern "C" void kernel_launch(void* const* d_in, const int* in_sizes, int n_in,
                              void* d_out, int out_size) {
  const float* inpt = (const float*)d_in[0];
  const int*   pn   = (const int*)d_in[1];
  const int*   pt   = (const int*)d_in[2];
  const float* ln_g = (const float*)d_in[3];
  const float* ln_b = (const float*)d_in[4];
  const float* Wq   = (const float*)d_in[5];
  const float* bq   = (const float*)d_in[6];
  const float* Wk   = (const float*)d_in[7];
  const float* bk   = (const float*)d_in[8];
  const float* Wv   = (const float*)d_in[9];
  const float* bv   = (const float*)d_in[10];
  const float* Wp   = (const float*)d_in[11];
  const float* bp   = (const float*)d_in[12];
  float* out = (float*)d_out;
  (void)in_sizes; (void)n_in; (void)out_size;

  const int smem_fused = 196608;           // K(64K) + V(64K) + W0(32K) + W1(32K)
  const int smem_proj  = 98304 + 256;
  cudaFuncSetAttribute(k_fused, cudaFuncAttributeMaxDynamicSharedMemorySize, smem_fused);
  cudaFuncSetAttribute(k_proj,  cudaFuncAttributeMaxDynamicSharedMemorySize, smem_proj);

  k_convert<<<256, 256>>>(Wq, Wk, Wv, Wp);
  k_fused<<<1024, 512, smem_fused>>>(inpt, pn, pt, ln_g, ln_b, bq, bk, bv);
  k_proj<<<dim3(2048, 2), 256, smem_proj>>>(inpt, pn, pt, bp, out);
}